// round 1
// baseline (speedup 1.0000x reference)
#include <cuda_runtime.h>

#define BATCH   64
#define IN_PN   20000
#define OUT_PN  5000
#define MNB     9
#define CIN     32
#define COUT    64
#define KDIM    (MNB * CIN)   /* 288 */
#define SSTRIDE 68            /* padded row stride in floats: float4-aligned, conflict-light */

// smem layout (floats):
//   Ws  [KDIM][SSTRIDE]  : W transposed  Ws[k][o]   (k = m*32+c)
//   Ins [KDIM][SSTRIDE]  : gathered in   Ins[k][b]
//   rs  [CIN ][SSTRIDE]  : residual r    rs[c][b]
//   wrs [CIN ][SSTRIDE]  : weight_res^T  wrs[c][o]
//   pm  [16]             : normalized |p| weights
//   nids[16] (as int)    : neighbor ids
#define SM_WS   0
#define SM_INS  (KDIM * SSTRIDE)
#define SM_RS   (2 * KDIM * SSTRIDE)
#define SM_WRS  (SM_RS + CIN * SSTRIDE)
#define SM_PM   (SM_WRS + CIN * SSTRIDE)
#define SM_NID  (SM_PM + 16)
#define SM_FLOATS (SM_NID + 16)

__global__ __launch_bounds__(256, 1)
void pconv_kernel(const float* __restrict__ in_pc,
                  const int*   __restrict__ nid_g,
                  const float* __restrict__ wts,
                  const float* __restrict__ bias,
                  const float* __restrict__ pnb,
                  const float* __restrict__ wres,
                  float* __restrict__ out)
{
    extern __shared__ float sm[];
    float* Ws  = sm + SM_WS;
    float* Ins = sm + SM_INS;
    float* rs  = sm + SM_RS;
    float* wrs = sm + SM_WRS;
    float* pm  = sm + SM_PM;
    int*   nids = (int*)(sm + SM_NID);

    const int p   = blockIdx.x;
    const int tid = threadIdx.x;

    // ---- neighbor ids + masked |p_neighbors| ----
    if (tid < MNB) {
        int nv = nid_g[p * MNB + tid];
        nids[tid] = nv;
        pm[tid] = (nv != IN_PN) ? fabsf(pnb[p * MNB + tid]) : 0.0f;
    }
    __syncthreads();
    if (tid == 0) {
        float s = 1e-8f;
        #pragma unroll
        for (int m = 0; m < MNB; m++) s += pm[m];
        float inv = 1.0f / s;
        #pragma unroll
        for (int m = 0; m < MNB; m++) pm[m] *= inv;
    }

    // ---- stage W[p] transposed: gmem [m][o][c] -> smem Ws[(m*32+c)][o] ----
    {
        const float* wp = wts + (size_t)p * (KDIM * COUT);
        #pragma unroll 8
        for (int i = 0; i < (KDIM * COUT) / 256; i++) {
            int idx = tid + i * 256;
            int m = idx >> 11;            // / (64*32)
            int o = (idx >> 5) & 63;
            int c = idx & 31;
            Ws[(m * CIN + c) * SSTRIDE + o] = wp[idx];
        }
    }

    // ---- stage weight_res transposed: [o][c] -> wrs[c][o] ----
    #pragma unroll
    for (int i = 0; i < (COUT * CIN) / 256; i++) {
        int idx = tid + i * 256;
        int o = idx >> 5, c = idx & 31;
        wrs[c * SSTRIDE + o] = wres[idx];
    }

    // ---- gather inputs: Ins[(m*32+c)][b] = in_pc[b, nid[m], c] (0 if pad) ----
    {
        #pragma unroll 8
        for (int i = 0; i < (BATCH * KDIM) / 256; i++) {
            int idx = tid + i * 256;
            int b = idx / KDIM;
            int k = idx - b * KDIM;       // m*32 + c
            int m = k >> 5;
            int c = k & 31;
            int nv = nids[m];
            float v = 0.0f;
            if (nv != IN_PN)
                v = in_pc[(size_t)b * (IN_PN * CIN) + (size_t)nv * CIN + c];
            Ins[k * SSTRIDE + b] = v;
        }
    }
    __syncthreads();

    // ---- residual pre-reduction: rs[c][b] = sum_m pm[m] * Ins[(m,c)][b] ----
    #pragma unroll
    for (int i = 0; i < (BATCH * CIN) / 256; i++) {
        int idx = tid + i * 256;
        int b = idx & 63;
        int c = idx >> 6;
        float acc = 0.0f;
        #pragma unroll
        for (int m = 0; m < MNB; m++)
            acc = fmaf(pm[m], Ins[(m * CIN + c) * SSTRIDE + b], acc);
        rs[c * SSTRIDE + b] = acc;
    }
    __syncthreads();

    // ---- main GEMM: thread tile 4b x 4o over k = 0..287 ----
    const int og = (tid & 15) * 4;
    const int bg = (tid >> 4) * 4;

    float acc00=0,acc01=0,acc02=0,acc03=0;
    float acc10=0,acc11=0,acc12=0,acc13=0;
    float acc20=0,acc21=0,acc22=0,acc23=0;
    float acc30=0,acc31=0,acc32=0,acc33=0;

    #pragma unroll 4
    for (int k = 0; k < KDIM; k++) {
        float4 a = *(const float4*)&Ins[k * SSTRIDE + bg];
        float4 w = *(const float4*)&Ws [k * SSTRIDE + og];
        acc00 = fmaf(a.x, w.x, acc00); acc01 = fmaf(a.x, w.y, acc01);
        acc02 = fmaf(a.x, w.z, acc02); acc03 = fmaf(a.x, w.w, acc03);
        acc10 = fmaf(a.y, w.x, acc10); acc11 = fmaf(a.y, w.y, acc11);
        acc12 = fmaf(a.y, w.z, acc12); acc13 = fmaf(a.y, w.w, acc13);
        acc20 = fmaf(a.z, w.x, acc20); acc21 = fmaf(a.z, w.y, acc21);
        acc22 = fmaf(a.z, w.z, acc22); acc23 = fmaf(a.z, w.w, acc23);
        acc30 = fmaf(a.w, w.x, acc30); acc31 = fmaf(a.w, w.y, acc31);
        acc32 = fmaf(a.w, w.z, acc32); acc33 = fmaf(a.w, w.w, acc33);
    }

    // ---- residual GEMM: 4b x 4o over c = 0..31 ----
    float r00=0,r01=0,r02=0,r03=0;
    float r10=0,r11=0,r12=0,r13=0;
    float r20=0,r21=0,r22=0,r23=0;
    float r30=0,r31=0,r32=0,r33=0;
    #pragma unroll
    for (int c = 0; c < CIN; c++) {
        float4 a = *(const float4*)&rs [c * SSTRIDE + bg];
        float4 w = *(const float4*)&wrs[c * SSTRIDE + og];
        r00 = fmaf(a.x, w.x, r00); r01 = fmaf(a.x, w.y, r01);
        r02 = fmaf(a.x, w.z, r02); r03 = fmaf(a.x, w.w, r03);
        r10 = fmaf(a.y, w.x, r10); r11 = fmaf(a.y, w.y, r11);
        r12 = fmaf(a.y, w.z, r12); r13 = fmaf(a.y, w.w, r13);
        r20 = fmaf(a.z, w.x, r20); r21 = fmaf(a.z, w.y, r21);
        r22 = fmaf(a.z, w.z, r22); r23 = fmaf(a.z, w.w, r23);
        r30 = fmaf(a.w, w.x, r30); r31 = fmaf(a.w, w.y, r31);
        r32 = fmaf(a.w, w.z, r32); r33 = fmaf(a.w, w.w, r33);
    }

    // ---- epilogue: out = sqrt(1-RR)*elu(conv+bias) + sqrt(RR)*res ----
    const float C = 0.70710678118654752f;  // sqrt(0.5) for both terms (RR=0.5)
    float4 bv = *(const float4*)&bias[(size_t)p * COUT + og];

    float conv[4][4] = {{acc00,acc01,acc02,acc03},
                        {acc10,acc11,acc12,acc13},
                        {acc20,acc21,acc22,acc23},
                        {acc30,acc31,acc32,acc33}};
    float resv[4][4] = {{r00,r01,r02,r03},
                        {r10,r11,r12,r13},
                        {r20,r21,r22,r23},
                        {r30,r31,r32,r33}};
    const float bb[4] = {bv.x, bv.y, bv.z, bv.w};

    #pragma unroll
    for (int i = 0; i < 4; i++) {
        float4 o4;
        float* po = &o4.x;
        #pragma unroll
        for (int j = 0; j < 4; j++) {
            float x = conv[i][j] + bb[j];
            x = (x > 0.0f) ? x : expm1f(x);          // elu, alpha=1
            po[j] = C * x + C * resv[i][j];
        }
        size_t off = ((size_t)(bg + i) * OUT_PN + p) * COUT + og;
        *(float4*)&out[off] = o4;
    }
}

extern "C" void kernel_launch(void* const* d_in, const int* in_sizes, int n_in,
                              void* d_out, int out_size)
{
    const float* in_pc = (const float*)d_in[0];
    const int*   nid   = (const int*)  d_in[1];
    const float* wts   = (const float*)d_in[2];
    const float* bias  = (const float*)d_in[3];
    const float* pnb   = (const float*)d_in[4];
    const float* wres  = (const float*)d_in[5];
    float* out = (float*)d_out;

    const int smem_bytes = SM_FLOATS * sizeof(float);   // ~174.2 KB
    cudaFuncSetAttribute(pconv_kernel,
                         cudaFuncAttributeMaxDynamicSharedMemorySize, smem_bytes);

    pconv_kernel<<<OUT_PN, 256, smem_bytes>>>(in_pc, nid, wts, bias, pnb, wres, out);
}

// round 2
// speedup vs baseline: 4.1935x; 4.1935x over previous
#include <cuda_runtime.h>

#define BATCH   64
#define IN_PN   20000
#define OUT_PN  5000
#define MNB     9
#define CIN     32
#define COUT    64
#define ST      68                 /* padded row stride (floats), float4-aligned */
#define SLF     (CIN * ST)         /* floats per 32x64 slice buffer = 2176 */

// ---- per-slice global->register loads (issued early for pipelining) ----
__device__ __forceinline__ void ldg_slice(const float* __restrict__ wp_m,
                                          const float* __restrict__ in_pc,
                                          int nv, int tid,
                                          float4& w0, float4& w1,
                                          float4& i0, float4& i1)
{
    const int o0 = tid >> 3;        // 0..31
    const int c4 = tid & 7;         // 0..7
    w0 = *(const float4*)(wp_m + (size_t)o0        * CIN + c4 * 4);
    w1 = *(const float4*)(wp_m + (size_t)(o0 + 32) * CIN + c4 * 4);
    if (nv != IN_PN) {
        const float* ip = in_pc + (size_t)nv * CIN + c4 * 4;
        i0 = *(const float4*)(ip + (size_t)o0        * ((size_t)IN_PN * CIN));
        i1 = *(const float4*)(ip + (size_t)(o0 + 32) * ((size_t)IN_PN * CIN));
    } else {
        i0 = make_float4(0.f, 0.f, 0.f, 0.f);
        i1 = make_float4(0.f, 0.f, 0.f, 0.f);
    }
}

// ---- register->smem transposed stores:  Wd[c][o], Id[c][b] ----
__device__ __forceinline__ void sts_slice(float* __restrict__ Wd,
                                          float* __restrict__ Id,
                                          int tid,
                                          float4 w0, float4 w1,
                                          float4 i0, float4 i1)
{
    const int o0 = tid >> 3;
    const int r  = (tid & 7) * 4;   // c base
    Wd[(r + 0) * ST + o0] = w0.x;  Wd[(r + 1) * ST + o0] = w0.y;
    Wd[(r + 2) * ST + o0] = w0.z;  Wd[(r + 3) * ST + o0] = w0.w;
    Wd[(r + 0) * ST + o0 + 32] = w1.x;  Wd[(r + 1) * ST + o0 + 32] = w1.y;
    Wd[(r + 2) * ST + o0 + 32] = w1.z;  Wd[(r + 3) * ST + o0 + 32] = w1.w;
    Id[(r + 0) * ST + o0] = i0.x;  Id[(r + 1) * ST + o0] = i0.y;
    Id[(r + 2) * ST + o0] = i0.z;  Id[(r + 3) * ST + o0] = i0.w;
    Id[(r + 0) * ST + o0 + 32] = i1.x;  Id[(r + 1) * ST + o0 + 32] = i1.y;
    Id[(r + 2) * ST + o0 + 32] = i1.z;  Id[(r + 3) * ST + o0 + 32] = i1.w;
}

// ---- 4b x 4o rank-32 update from one slice ----
__device__ __forceinline__ void gemm_slice(const float* __restrict__ Wc,
                                           const float* __restrict__ Ic,
                                           int og, int bg, float acc[16])
{
    #pragma unroll 8
    for (int k = 0; k < CIN; k++) {
        float4 a = *(const float4*)&Ic[k * ST + bg];
        float4 w = *(const float4*)&Wc[k * ST + og];
        acc[ 0] = fmaf(a.x, w.x, acc[ 0]); acc[ 1] = fmaf(a.x, w.y, acc[ 1]);
        acc[ 2] = fmaf(a.x, w.z, acc[ 2]); acc[ 3] = fmaf(a.x, w.w, acc[ 3]);
        acc[ 4] = fmaf(a.y, w.x, acc[ 4]); acc[ 5] = fmaf(a.y, w.y, acc[ 5]);
        acc[ 6] = fmaf(a.y, w.z, acc[ 6]); acc[ 7] = fmaf(a.y, w.w, acc[ 7]);
        acc[ 8] = fmaf(a.z, w.x, acc[ 8]); acc[ 9] = fmaf(a.z, w.y, acc[ 9]);
        acc[10] = fmaf(a.z, w.z, acc[10]); acc[11] = fmaf(a.z, w.w, acc[11]);
        acc[12] = fmaf(a.w, w.x, acc[12]); acc[13] = fmaf(a.w, w.y, acc[13]);
        acc[14] = fmaf(a.w, w.z, acc[14]); acc[15] = fmaf(a.w, w.w, acc[15]);
    }
}

__global__ __launch_bounds__(256, 2)
void pconv_kernel(const float* __restrict__ in_pc,
                  const int*   __restrict__ nid_g,
                  const float* __restrict__ wts,
                  const float* __restrict__ bias,
                  const float* __restrict__ pnb,
                  const float* __restrict__ wres,
                  float* __restrict__ out)
{
    __shared__ float sm[4 * SLF + 32];
    float* Wb0 = sm;
    float* Wb1 = sm + SLF;
    float* Ib0 = sm + 2 * SLF;
    float* Ib1 = sm + 3 * SLF;
    float* pm  = sm + 4 * SLF;
    int*   nids = (int*)(sm + 4 * SLF + 16);

    const int p   = blockIdx.x;
    const int tid = threadIdx.x;

    // neighbor ids + masked |p| weights
    if (tid < MNB) {
        int nv = nid_g[p * MNB + tid];
        nids[tid] = nv;
        pm[tid] = (nv != IN_PN) ? fabsf(pnb[p * MNB + tid]) : 0.0f;
    }
    __syncthreads();
    if (tid == 0) {
        float s = 1e-8f;
        #pragma unroll
        for (int m = 0; m < MNB; m++) s += pm[m];
        float inv = 1.0f / s;
        #pragma unroll
        for (int m = 0; m < MNB; m++) pm[m] *= inv;
    }

    const float* wp = wts + (size_t)p * (MNB * CIN * COUT);

    // prologue: stage slice 0
    {
        float4 w0, w1, i0, i1;
        ldg_slice(wp, in_pc, nids[0], tid, w0, w1, i0, i1);
        sts_slice(Wb0, Ib0, tid, w0, w1, i0, i1);
    }
    __syncthreads();

    const int og = (tid & 15) * 4;
    const int bg = (tid >> 4) * 4;

    float acc[16];
    #pragma unroll
    for (int i = 0; i < 16; i++) acc[i] = 0.0f;
    float rs[8];
    #pragma unroll
    for (int i = 0; i < 8; i++) rs[i] = 0.0f;

    #pragma unroll
    for (int m = 0; m < MNB; m++) {
        const int cur = m & 1;
        float* Wc = cur ? Wb1 : Wb0;
        float* Ic = cur ? Ib1 : Ib0;
        float* Wn = cur ? Wb0 : Wb1;
        float* In = cur ? Ib0 : Ib1;

        float4 w0, w1, i0, i1;
        if (m < MNB - 1)
            ldg_slice(wp + (size_t)(m + 1) * (CIN * COUT), in_pc, nids[m + 1],
                      tid, w0, w1, i0, i1);

        gemm_slice(Wc, Ic, og, bg, acc);

        // residual pre-reduction: rs owns 8 fixed (c,b) elements
        const float pmv = pm[m];
        #pragma unroll
        for (int i = 0; i < 8; i++) {
            int e = tid + i * 256;
            rs[i] = fmaf(pmv, Ic[(e >> 6) * ST + (e & 63)], rs[i]);
        }

        if (m < MNB - 1)
            sts_slice(Wn, In, tid, w0, w1, i0, i1);
        __syncthreads();
    }

    // stage residual operand rs -> Ib0, weight_res^T -> Wb0 (buffers are free)
    #pragma unroll
    for (int i = 0; i < 8; i++) {
        int e = tid + i * 256;
        Ib0[(e >> 6) * ST + (e & 63)] = rs[i];
    }
    {
        const int o0 = tid >> 3;
        const int r  = (tid & 7) * 4;
        float4 v0 = *(const float4*)(wres + (size_t)o0 * CIN + (tid & 7) * 4);
        float4 v1 = *(const float4*)(wres + (size_t)(o0 + 32) * CIN + (tid & 7) * 4);
        Wb0[(r + 0) * ST + o0] = v0.x;  Wb0[(r + 1) * ST + o0] = v0.y;
        Wb0[(r + 2) * ST + o0] = v0.z;  Wb0[(r + 3) * ST + o0] = v0.w;
        Wb0[(r + 0) * ST + o0 + 32] = v1.x;  Wb0[(r + 1) * ST + o0 + 32] = v1.y;
        Wb0[(r + 2) * ST + o0 + 32] = v1.z;  Wb0[(r + 3) * ST + o0 + 32] = v1.w;
    }
    __syncthreads();

    // residual GEMM (K = 32)
    float racc[16];
    #pragma unroll
    for (int i = 0; i < 16; i++) racc[i] = 0.0f;
    gemm_slice(Wb0, Ib0, og, bg, racc);

    // epilogue: out = sqrt(1-RR)*elu(conv+bias) + sqrt(RR)*res
    const float C = 0.70710678118654752f;
    float4 bv = *(const float4*)&bias[(size_t)p * COUT + og];
    const float bb[4] = { bv.x, bv.y, bv.z, bv.w };

    #pragma unroll
    for (int i = 0; i < 4; i++) {
        float4 o4;
        float* po = &o4.x;
        #pragma unroll
        for (int j = 0; j < 4; j++) {
            float x = acc[i * 4 + j] + bb[j];
            x = (x > 0.0f) ? x : expm1f(x);          // elu, alpha = 1
            po[j] = C * x + C * racc[i * 4 + j];
        }
        size_t off = ((size_t)(bg + i) * OUT_PN + p) * COUT + og;
        *(float4*)&out[off] = o4;
    }
}

extern "C" void kernel_launch(void* const* d_in, const int* in_sizes, int n_in,
                              void* d_out, int out_size)
{
    const float* in_pc = (const float*)d_in[0];
    const int*   nid   = (const int*)  d_in[1];
    const float* wts   = (const float*)d_in[2];
    const float* bias  = (const float*)d_in[3];
    const float* pnb   = (const float*)d_in[4];
    const float* wres  = (const float*)d_in[5];
    float* out = (float*)d_out;

    pconv_kernel<<<OUT_PN, 256>>>(in_pc, nid, wts, bias, pnb, wres, out);
}